// round 3
// baseline (speedup 1.0000x reference)
#include <cuda_runtime.h>

#define BATCH 2
#define SEQ   2048
#define DM    768
#define NH    12
#define DK    64
#define MROWS (BATCH*SEQ)
#define LDP   68   // padded smem row stride (floats), keeps float4 alignment

// Scratch (allocation-free rule: __device__ globals)
__device__ float g_q[MROWS*DM];
__device__ float g_k[MROWS*DM];
__device__ float g_v[MROWS*DM];
__device__ float g_a[MROWS*DM];

// ---------------------------------------------------------------------------
// C[M,N] = A[M,K] @ B[N,K]^T   (A row-major, B row-major "weights (out,in)")
// 64x64 tile, BK=16, 256 threads, 4x4 per thread.
// ---------------------------------------------------------------------------
__global__ __launch_bounds__(256) void gemm64(const float* __restrict__ A,
                                              const float* __restrict__ Bm,
                                              float* __restrict__ C,
                                              int M, int N, int K)
{
    __shared__ float As[16][64];
    __shared__ float Bs[16][64];
    const int tid = threadIdx.x;
    const int tx = tid & 15, ty = tid >> 4;
    const int bm = blockIdx.y * 64, bn = blockIdx.x * 64;
    const int lr = tid >> 2;          // 0..63 tile row
    const int lc = (tid & 3) << 2;    // k offset 0,4,8,12

    float acc[4][4] = {};
    const float* Aptr = A  + (long)(bm + lr) * K + lc;
    const float* Bptr = Bm + (long)(bn + lr) * K + lc;

    for (int kt = 0; kt < K; kt += 16) {
        float4 av = *(const float4*)(Aptr + kt);
        float4 bv = *(const float4*)(Bptr + kt);
        As[lc+0][lr]=av.x; As[lc+1][lr]=av.y; As[lc+2][lr]=av.z; As[lc+3][lr]=av.w;
        Bs[lc+0][lr]=bv.x; Bs[lc+1][lr]=bv.y; Bs[lc+2][lr]=bv.z; Bs[lc+3][lr]=bv.w;
        __syncthreads();
#pragma unroll
        for (int kk = 0; kk < 16; kk++) {
            float4 a = *(const float4*)&As[kk][ty<<2];
            float4 b = *(const float4*)&Bs[kk][tx<<2];
            float ar[4] = {a.x,a.y,a.z,a.w};
            float br[4] = {b.x,b.y,b.z,b.w};
#pragma unroll
            for (int i=0;i<4;i++)
#pragma unroll
                for (int j=0;j<4;j++) acc[i][j] = fmaf(ar[i], br[j], acc[i][j]);
        }
        __syncthreads();
    }
#pragma unroll
    for (int i=0;i<4;i++) {
        float4 o = make_float4(acc[i][0],acc[i][1],acc[i][2],acc[i][3]);
        *(float4*)&C[(long)(bm + (ty<<2) + i) * N + bn + (tx<<2)] = o;
    }
}

// ---------------------------------------------------------------------------
// Causal flash attention: BQ=64 queries per CTA, BK=64 keys per iter.
// Q/K/V stored as [b*S][DM] rows with head slice at h*DK.
// ---------------------------------------------------------------------------
__global__ __launch_bounds__(256) void flash_kernel()
{
    extern __shared__ float sm[];
    float* Qst = sm;                 // [d][r]   d-major, pre-scaled by 1/8
    float* Kst = sm + 64*LDP;        // [d][c]   d-major
    float* Vs  = sm + 2*64*LDP;      // [key][dim]
    float* Ps  = sm + 3*64*LDP;      // [r][key]

    const int tid = threadIdx.x;
    const int tx = tid & 15, ty = tid >> 4;
    const int qblk = blockIdx.x;
    const int h = blockIdx.y, b = blockIdx.z;
    const int qg0 = qblk * 64;
    const int headoff = h * DK;
    const float NEG_INF = __int_as_float(0xff800000);

    // Load Q tile (transposed to d-major, pre-scaled by 1/sqrt(64)=0.125)
#pragma unroll
    for (int u = 0; u < 4; u++) {
        int lin = tid + u * 256;          // 0..1023 float4 units
        int r = lin >> 4;                 // 0..63
        int c = (lin & 15) << 2;          // 0..60
        float4 v = *(const float4*)&g_q[(long)(b*SEQ + qg0 + r)*DM + headoff + c];
        Qst[(c+0)*LDP + r] = v.x * 0.125f;
        Qst[(c+1)*LDP + r] = v.y * 0.125f;
        Qst[(c+2)*LDP + r] = v.z * 0.125f;
        Qst[(c+3)*LDP + r] = v.w * 0.125f;
    }

    float m_i[4], l_i[4], O[4][4];
#pragma unroll
    for (int i=0;i<4;i++){ m_i[i]=NEG_INF; l_i[i]=0.f;
#pragma unroll
        for (int j=0;j<4;j++) O[i][j]=0.f; }

    for (int jb = 0; jb <= qblk; jb++) {
        __syncthreads();   // prev-iter consumers done (also covers Q-load on jb=0)

        // Load K (transposed) and V (natural)
#pragma unroll
        for (int u = 0; u < 4; u++) {
            int lin = tid + u * 256;
            int r = lin >> 4;
            int c = (lin & 15) << 2;
            long grow = (long)(b*SEQ + jb*64 + r)*DM + headoff + c;
            float4 kv = *(const float4*)&g_k[grow];
            Kst[(c+0)*LDP + r] = kv.x;
            Kst[(c+1)*LDP + r] = kv.y;
            Kst[(c+2)*LDP + r] = kv.z;
            Kst[(c+3)*LDP + r] = kv.w;
            float4 vv = *(const float4*)&g_v[grow];
            *(float4*)&Vs[r*LDP + c] = vv;
        }
        __syncthreads();

        // S = Q K^T (64x64), each thread 4x4
        float sacc[4][4] = {};
#pragma unroll 8
        for (int kk = 0; kk < 64; kk++) {
            float4 q = *(const float4*)&Qst[kk*LDP + (ty<<2)];
            float4 k = *(const float4*)&Kst[kk*LDP + (tx<<2)];
            float qr[4] = {q.x,q.y,q.z,q.w};
            float kr[4] = {k.x,k.y,k.z,k.w};
#pragma unroll
            for (int i=0;i<4;i++)
#pragma unroll
                for (int j=0;j<4;j++) sacc[i][j] = fmaf(qr[i], kr[j], sacc[i][j]);
        }

        if (jb == qblk) {   // diagonal block: causal mask (local indices)
#pragma unroll
            for (int i=0;i<4;i++)
#pragma unroll
                for (int j=0;j<4;j++)
                    if (((tx<<2)+j) > ((ty<<2)+i)) sacc[i][j] = NEG_INF;
        }

        // Online softmax per row (row owned by 16 lanes, aligned half-warp)
#pragma unroll
        for (int i=0;i<4;i++) {
            float ml = fmaxf(fmaxf(sacc[i][0],sacc[i][1]), fmaxf(sacc[i][2],sacc[i][3]));
            ml = fmaxf(ml, __shfl_xor_sync(0xffffffffu, ml, 1));
            ml = fmaxf(ml, __shfl_xor_sync(0xffffffffu, ml, 2));
            ml = fmaxf(ml, __shfl_xor_sync(0xffffffffu, ml, 4));
            ml = fmaxf(ml, __shfl_xor_sync(0xffffffffu, ml, 8));
            float mn = fmaxf(m_i[i], ml);
            float al = __expf(m_i[i] - mn);
            m_i[i] = mn;
            float ps = 0.f;
#pragma unroll
            for (int j=0;j<4;j++) { float p = __expf(sacc[i][j] - mn); sacc[i][j] = p; ps += p; }
            ps += __shfl_xor_sync(0xffffffffu, ps, 1);
            ps += __shfl_xor_sync(0xffffffffu, ps, 2);
            ps += __shfl_xor_sync(0xffffffffu, ps, 4);
            ps += __shfl_xor_sync(0xffffffffu, ps, 8);
            l_i[i] = l_i[i]*al + ps;
#pragma unroll
            for (int j=0;j<4;j++) O[i][j] *= al;
            *(float4*)&Ps[((ty<<2)+i)*LDP + (tx<<2)] =
                make_float4(sacc[i][0],sacc[i][1],sacc[i][2],sacc[i][3]);
        }
        __syncthreads();

        // O += P @ V
#pragma unroll 8
        for (int kk = 0; kk < 64; kk++) {
            float4 vv = *(const float4*)&Vs[kk*LDP + (tx<<2)];
            float vr[4] = {vv.x,vv.y,vv.z,vv.w};
            float pr[4];
#pragma unroll
            for (int i=0;i<4;i++) pr[i] = Ps[((ty<<2)+i)*LDP + kk];
#pragma unroll
            for (int i=0;i<4;i++)
#pragma unroll
                for (int j=0;j<4;j++) O[i][j] = fmaf(pr[i], vr[j], O[i][j]);
        }
    }

    // Epilogue: normalize + write to interleaved attention-out buffer
#pragma unroll
    for (int i=0;i<4;i++) {
        float inv = 1.f / l_i[i];
        float4 o = make_float4(O[i][0]*inv, O[i][1]*inv, O[i][2]*inv, O[i][3]*inv);
        *(float4*)&g_a[(long)(b*SEQ + qg0 + (ty<<2)+i)*DM + headoff + (tx<<2)] = o;
    }
}

// ---------------------------------------------------------------------------
extern "C" void kernel_launch(void* const* d_in, const int* in_sizes, int n_in,
                              void* d_out, int out_size)
{
    const float* x  = (const float*)d_in[0];
    const float* wq = (const float*)d_in[1];
    const float* wk = (const float*)d_in[2];
    const float* wv = (const float*)d_in[3];
    const float* wo = (const float*)d_in[4];
    float* out = (float*)d_out;

    float *q, *k, *v, *a;
    cudaGetSymbolAddress((void**)&q, g_q);
    cudaGetSymbolAddress((void**)&k, g_k);
    cudaGetSymbolAddress((void**)&v, g_v);
    cudaGetSymbolAddress((void**)&a, g_a);

    const int smem_bytes = 4 * 64 * LDP * sizeof(float);  // 69632
    cudaFuncSetAttribute(flash_kernel, cudaFuncAttributeMaxDynamicSharedMemorySize, smem_bytes);

    dim3 gg(DM/64, MROWS/64);
    gemm64<<<gg, 256>>>(x, wq, q, MROWS, DM, DM);
    gemm64<<<gg, 256>>>(x, wk, k, MROWS, DM, DM);
    gemm64<<<gg, 256>>>(x, wv, v, MROWS, DM, DM);

    flash_kernel<<<dim3(SEQ/64, NH, BATCH), 256, smem_bytes>>>();

    gemm64<<<gg, 256>>>(a, wo, out, MROWS, DM, DM);
}

// round 5
// speedup vs baseline: 1.4670x; 1.4670x over previous
#include <cuda_runtime.h>
#include <cstdint>

#define BATCH 2
#define SEQ   2048
#define DM    768
#define NH    12
#define DK    64
#define MROWS (BATCH*SEQ)
#define LDP   68

// Scratch (allocation-free rule: __device__ globals)
__device__ float g_q[MROWS*DM];
__device__ float g_k[MROWS*DM];
__device__ float g_v[MROWS*DM];
__device__ float g_a[MROWS*DM];

// ============================================================================
// helpers
// ============================================================================
// pack two f32 -> bf16x2 (x in low half, y in high half)
__device__ __forceinline__ uint32_t bfpack(float x, float y) {
    uint32_t r;
    asm("cvt.rn.bf16x2.f32 %0, %1, %2;" : "=r"(r) : "f"(y), "f"(x));
    return r;
}
// D += A(16x16 bf16) * B(16x8 bf16)^T-col, fp32 accum
__device__ __forceinline__ void mma16816(float* c, const uint32_t* a, const uint32_t* b) {
    asm volatile(
        "mma.sync.aligned.m16n8k16.row.col.f32.bf16.bf16.f32 "
        "{%0,%1,%2,%3}, {%4,%5,%6,%7}, {%8,%9}, {%0,%1,%2,%3};"
        : "+f"(c[0]), "+f"(c[1]), "+f"(c[2]), "+f"(c[3])
        : "r"(a[0]), "r"(a[1]), "r"(a[2]), "r"(a[3]), "r"(b[0]), "r"(b[1]));
}

// ============================================================================
// Tensor-core GEMM: C[M,768] = A[M,768] @ W[768,768]^T   (C[m,n]=sum_k A[m,k]W[n,k])
// bf16 3-product split (hi/lo), mma.sync m16n8k16. 128x128 CTA tile, BK=32.
// 8 warps: (2 m) x (4 n), each warp 64x32 output in registers.
// grid = (6, M/128), 256 threads.
// ============================================================================
#define SROW 18   // smem row stride in b32 words (32 bf16 data + 4 pad = 72B)

__global__ __launch_bounds__(256, 2) void gemm_mma(const float* __restrict__ A,
                                                   const float* __restrict__ Bm,
                                                   float* __restrict__ C)
{
    __shared__ uint32_t Ah[128*SROW], Al[128*SROW], Bh[128*SROW], Bl[128*SROW];

    const int tid  = threadIdx.x;
    const int warp = tid >> 5, lane = tid & 31;
    const int g = lane >> 2, t = lane & 3;          // fragment group / thread-in-group
    const int wm = warp >> 2, wn = warp & 3;        // warp tile coords
    const int m0 = blockIdx.y * 128, n0 = blockIdx.x * 128;

    float c[4][4][4];
#pragma unroll
    for (int i = 0; i < 4; i++)
#pragma unroll
        for (int j = 0; j < 4; j++)
#pragma unroll
            for (int r = 0; r < 4; r++) c[i][j][r] = 0.f;

    for (int kc = 0; kc < DM / 32; kc++) {
        __syncthreads();
        // ---- load 128x32 fp32 tiles of A and W, split into bf16 hi/lo ----
#pragma unroll
        for (int u = 0; u < 4; u++) {
            int lin = tid + u * 256;        // 0..1023 float4 slots
            int row = lin >> 3;             // 0..127
            int c4  = lin & 7;              // float4 within row
            {
                float4 v = *(const float4*)&A[(long)(m0 + row) * DM + kc * 32 + c4 * 4];
                uint32_t h0 = bfpack(v.x, v.y), h1 = bfpack(v.z, v.w);
                float lx = v.x - __uint_as_float(h0 << 16);
                float ly = v.y - __uint_as_float(h0 & 0xffff0000u);
                float lz = v.z - __uint_as_float(h1 << 16);
                float lw = v.w - __uint_as_float(h1 & 0xffff0000u);
                Ah[row * SROW + c4 * 2]     = h0;
                Ah[row * SROW + c4 * 2 + 1] = h1;
                Al[row * SROW + c4 * 2]     = bfpack(lx, ly);
                Al[row * SROW + c4 * 2 + 1] = bfpack(lz, lw);
            }
            {
                float4 v = *(const float4*)&Bm[(long)(n0 + row) * DM + kc * 32 + c4 * 4];
                uint32_t h0 = bfpack(v.x, v.y), h1 = bfpack(v.z, v.w);
                float lx = v.x - __uint_as_float(h0 << 16);
                float ly = v.y - __uint_as_float(h0 & 0xffff0000u);
                float lz = v.z - __uint_as_float(h1 << 16);
                float lw = v.w - __uint_as_float(h1 & 0xffff0000u);
                Bh[row * SROW + c4 * 2]     = h0;
                Bh[row * SROW + c4 * 2 + 1] = h1;
                Bl[row * SROW + c4 * 2]     = bfpack(lx, ly);
                Bl[row * SROW + c4 * 2 + 1] = bfpack(lz, lw);
            }
        }
        __syncthreads();

        // ---- 2 k-steps of 16 ----
#pragma unroll
        for (int ks = 0; ks < 2; ks++) {
            uint32_t bh[4][2], bl[4][2];
#pragma unroll
            for (int nt = 0; nt < 4; nt++) {
                int n = wn * 32 + nt * 8 + g;
                int w = n * SROW + ks * 8 + t;
                bh[nt][0] = Bh[w]; bh[nt][1] = Bh[w + 4];
                bl[nt][0] = Bl[w]; bl[nt][1] = Bl[w + 4];
            }
#pragma unroll
            for (int mt = 0; mt < 4; mt++) {
                int r = wm * 64 + mt * 16 + g;
                int w = r * SROW + ks * 8 + t;
                uint32_t ah[4] = { Ah[w], Ah[w + 8 * SROW], Ah[w + 4], Ah[w + 8 * SROW + 4] };
                uint32_t al[4] = { Al[w], Al[w + 8 * SROW], Al[w + 4], Al[w + 8 * SROW + 4] };
#pragma unroll
                for (int nt = 0; nt < 4; nt++) {
                    mma16816(c[mt][nt], ah, bh[nt]);
                    mma16816(c[mt][nt], al, bh[nt]);
                    mma16816(c[mt][nt], ah, bl[nt]);
                }
            }
        }
    }

    // ---- epilogue ----
#pragma unroll
    for (int mt = 0; mt < 4; mt++) {
#pragma unroll
        for (int nt = 0; nt < 4; nt++) {
            int row = m0 + wm * 64 + mt * 16 + g;
            int col = n0 + wn * 32 + nt * 8 + t * 2;
            *(float2*)&C[(long)row * DM + col]       = make_float2(c[mt][nt][0], c[mt][nt][1]);
            *(float2*)&C[(long)(row + 8) * DM + col] = make_float2(c[mt][nt][2], c[mt][nt][3]);
        }
    }
}

// ---------------------------------------------------------------------------
// Causal flash attention (unchanged fp32 path): BQ=64, BK=64.
// ---------------------------------------------------------------------------
__global__ __launch_bounds__(256) void flash_kernel()
{
    extern __shared__ float sm[];
    float* Qst = sm;
    float* Kst = sm + 64*LDP;
    float* Vs  = sm + 2*64*LDP;
    float* Ps  = sm + 3*64*LDP;

    const int tid = threadIdx.x;
    const int tx = tid & 15, ty = tid >> 4;
    const int qblk = blockIdx.x;
    const int h = blockIdx.y, b = blockIdx.z;
    const int qg0 = qblk * 64;
    const int headoff = h * DK;
    const float NEG_INF = __int_as_float(0xff800000);

#pragma unroll
    for (int u = 0; u < 4; u++) {
        int lin = tid + u * 256;
        int r = lin >> 4;
        int c = (lin & 15) << 2;
        float4 v = *(const float4*)&g_q[(long)(b*SEQ + qg0 + r)*DM + headoff + c];
        Qst[(c+0)*LDP + r] = v.x * 0.125f;
        Qst[(c+1)*LDP + r] = v.y * 0.125f;
        Qst[(c+2)*LDP + r] = v.z * 0.125f;
        Qst[(c+3)*LDP + r] = v.w * 0.125f;
    }

    float m_i[4], l_i[4], O[4][4];
#pragma unroll
    for (int i=0;i<4;i++){ m_i[i]=NEG_INF; l_i[i]=0.f;
#pragma unroll
        for (int j=0;j<4;j++) O[i][j]=0.f; }

    for (int jb = 0; jb <= qblk; jb++) {
        __syncthreads();
#pragma unroll
        for (int u = 0; u < 4; u++) {
            int lin = tid + u * 256;
            int r = lin >> 4;
            int c = (lin & 15) << 2;
            long grow = (long)(b*SEQ + jb*64 + r)*DM + headoff + c;
            float4 kv = *(const float4*)&g_k[grow];
            Kst[(c+0)*LDP + r] = kv.x;
            Kst[(c+1)*LDP + r] = kv.y;
            Kst[(c+2)*LDP + r] = kv.z;
            Kst[(c+3)*LDP + r] = kv.w;
            float4 vv = *(const float4*)&g_v[grow];
            *(float4*)&Vs[r*LDP + c] = vv;
        }
        __syncthreads();

        float sacc[4][4] = {};
#pragma unroll 8
        for (int kk = 0; kk < 64; kk++) {
            float4 q = *(const float4*)&Qst[kk*LDP + (ty<<2)];
            float4 k = *(const float4*)&Kst[kk*LDP + (tx<<2)];
            float qr[4] = {q.x,q.y,q.z,q.w};
            float kr[4] = {k.x,k.y,k.z,k.w};
#pragma unroll
            for (int i=0;i<4;i++)
#pragma unroll
                for (int j=0;j<4;j++) sacc[i][j] = fmaf(qr[i], kr[j], sacc[i][j]);
        }

        if (jb == qblk) {
#pragma unroll
            for (int i=0;i<4;i++)
#pragma unroll
                for (int j=0;j<4;j++)
                    if (((tx<<2)+j) > ((ty<<2)+i)) sacc[i][j] = NEG_INF;
        }

#pragma unroll
        for (int i=0;i<4;i++) {
            float ml = fmaxf(fmaxf(sacc[i][0],sacc[i][1]), fmaxf(sacc[i][2],sacc[i][3]));
            ml = fmaxf(ml, __shfl_xor_sync(0xffffffffu, ml, 1));
            ml = fmaxf(ml, __shfl_xor_sync(0xffffffffu, ml, 2));
            ml = fmaxf(ml, __shfl_xor_sync(0xffffffffu, ml, 4));
            ml = fmaxf(ml, __shfl_xor_sync(0xffffffffu, ml, 8));
            float mn = fmaxf(m_i[i], ml);
            float al = __expf(m_i[i] - mn);
            m_i[i] = mn;
            float ps = 0.f;
#pragma unroll
            for (int j=0;j<4;j++) { float p = __expf(sacc[i][j] - mn); sacc[i][j] = p; ps += p; }
            ps += __shfl_xor_sync(0xffffffffu, ps, 1);
            ps += __shfl_xor_sync(0xffffffffu, ps, 2);
            ps += __shfl_xor_sync(0xffffffffu, ps, 4);
            ps += __shfl_xor_sync(0xffffffffu, ps, 8);
            l_i[i] = l_i[i]*al + ps;
#pragma unroll
            for (int j=0;j<4;j++) O[i][j] *= al;
            *(float4*)&Ps[((ty<<2)+i)*LDP + (tx<<2)] =
                make_float4(sacc[i][0],sacc[i][1],sacc[i][2],sacc[i][3]);
        }
        __syncthreads();

#pragma unroll 8
        for (int kk = 0; kk < 64; kk++) {
            float4 vv = *(const float4*)&Vs[kk*LDP + (tx<<2)];
            float vr[4] = {vv.x,vv.y,vv.z,vv.w};
            float pr[4];
#pragma unroll
            for (int i=0;i<4;i++) pr[i] = Ps[((ty<<2)+i)*LDP + kk];
#pragma unroll
            for (int i=0;i<4;i++)
#pragma unroll
                for (int j=0;j<4;j++) O[i][j] = fmaf(pr[i], vr[j], O[i][j]);
        }
    }

#pragma unroll
    for (int i=0;i<4;i++) {
        float inv = 1.f / l_i[i];
        float4 o = make_float4(O[i][0]*inv, O[i][1]*inv, O[i][2]*inv, O[i][3]*inv);
        *(float4*)&g_a[(long)(b*SEQ + qg0 + (ty<<2)+i)*DM + headoff + (tx<<2)] = o;
    }
}

// ---------------------------------------------------------------------------
extern "C" void kernel_launch(void* const* d_in, const int* in_sizes, int n_in,
                              void* d_out, int out_size)
{
    const float* x  = (const float*)d_in[0];
    const float* wq = (const float*)d_in[1];
    const float* wk = (const float*)d_in[2];
    const float* wv = (const float*)d_in[3];
    const float* wo = (const float*)d_in[4];
    float* out = (float*)d_out;

    float *q, *k, *v, *a;
    cudaGetSymbolAddress((void**)&q, g_q);
    cudaGetSymbolAddress((void**)&k, g_k);
    cudaGetSymbolAddress((void**)&v, g_v);
    cudaGetSymbolAddress((void**)&a, g_a);

    const int fl_smem = 4 * 64 * LDP * sizeof(float);
    cudaFuncSetAttribute(flash_kernel, cudaFuncAttributeMaxDynamicSharedMemorySize, fl_smem);

    dim3 gg(DM / 128, MROWS / 128);  // (6, 32)
    gemm_mma<<<gg, 256>>>(x, wq, q);
    gemm_mma<<<gg, 256>>>(x, wk, k);
    gemm_mma<<<gg, 256>>>(x, wv, v);

    flash_kernel<<<dim3(SEQ/64, NH, BATCH), 256, fl_smem>>>();

    gemm_mma<<<gg, 256>>>(a, wo, out);
}

// round 7
// speedup vs baseline: 2.3132x; 1.5768x over previous
#include <cuda_runtime.h>
#include <cstdint>

#define BATCH 2
#define SEQ   2048
#define DM    768
#define NH    12
#define DK    64
#define MROWS (BATCH*SEQ)

// Scratch (allocation-free rule: __device__ globals)
__device__ float g_q[MROWS*DM];
__device__ float g_k[MROWS*DM];
__device__ float g_v[MROWS*DM];
__device__ float g_a[MROWS*DM];

// ============================================================================
// helpers
// ============================================================================
// pack two f32 -> bf16x2 (x in LOW half, y in HIGH half)
__device__ __forceinline__ uint32_t bfpack(float x, float y) {
    uint32_t r;
    asm("cvt.rn.bf16x2.f32 %0, %1, %2;" : "=r"(r) : "f"(y), "f"(x));
    return r;
}
__device__ __forceinline__ float lo_of(uint32_t p)  { return __uint_as_float(p << 16); }        // low bf16 as f32
__device__ __forceinline__ float hi_of(uint32_t p)  { return __uint_as_float(p & 0xffff0000u); } // high bf16 as f32
__device__ __forceinline__ uint16_t bf1(float x) {
    uint16_t u; asm("cvt.rn.bf16.f32 %0, %1;" : "=h"(u) : "f"(x)); return u;
}
__device__ __forceinline__ float bf1v(uint16_t u) { return __uint_as_float(((uint32_t)u) << 16); }

// D += A(16x16 bf16) * B(16x8 bf16 col), fp32 accum
__device__ __forceinline__ void mma16816(float* c, const uint32_t* a, const uint32_t* b) {
    asm volatile(
        "mma.sync.aligned.m16n8k16.row.col.f32.bf16.bf16.f32 "
        "{%0,%1,%2,%3}, {%4,%5,%6,%7}, {%8,%9}, {%0,%1,%2,%3};"
        : "+f"(c[0]), "+f"(c[1]), "+f"(c[2]), "+f"(c[3])
        : "r"(a[0]), "r"(a[1]), "r"(a[2]), "r"(a[3]), "r"(b[0]), "r"(b[1]));
}

// ============================================================================
// Tensor-core GEMM: C[M,768] = A[M,768] @ W[768,768]^T  (unchanged from R5)
// ============================================================================
#define SROW 18

__global__ __launch_bounds__(256, 2) void gemm_mma(const float* __restrict__ A,
                                                   const float* __restrict__ Bm,
                                                   float* __restrict__ C)
{
    __shared__ uint32_t Ah[128*SROW], Al[128*SROW], Bh[128*SROW], Bl[128*SROW];

    const int tid  = threadIdx.x;
    const int warp = tid >> 5, lane = tid & 31;
    const int g = lane >> 2, t = lane & 3;
    const int wm = warp >> 2, wn = warp & 3;
    const int m0 = blockIdx.y * 128, n0 = blockIdx.x * 128;

    float c[4][4][4];
#pragma unroll
    for (int i = 0; i < 4; i++)
#pragma unroll
        for (int j = 0; j < 4; j++)
#pragma unroll
            for (int r = 0; r < 4; r++) c[i][j][r] = 0.f;

    for (int kc = 0; kc < DM / 32; kc++) {
        __syncthreads();
#pragma unroll
        for (int u = 0; u < 4; u++) {
            int lin = tid + u * 256;
            int row = lin >> 3;
            int c4  = lin & 7;
            {
                float4 v = *(const float4*)&A[(long)(m0 + row) * DM + kc * 32 + c4 * 4];
                uint32_t h0 = bfpack(v.x, v.y), h1 = bfpack(v.z, v.w);
                Ah[row * SROW + c4 * 2]     = h0;
                Ah[row * SROW + c4 * 2 + 1] = h1;
                Al[row * SROW + c4 * 2]     = bfpack(v.x - lo_of(h0), v.y - hi_of(h0));
                Al[row * SROW + c4 * 2 + 1] = bfpack(v.z - lo_of(h1), v.w - hi_of(h1));
            }
            {
                float4 v = *(const float4*)&Bm[(long)(n0 + row) * DM + kc * 32 + c4 * 4];
                uint32_t h0 = bfpack(v.x, v.y), h1 = bfpack(v.z, v.w);
                Bh[row * SROW + c4 * 2]     = h0;
                Bh[row * SROW + c4 * 2 + 1] = h1;
                Bl[row * SROW + c4 * 2]     = bfpack(v.x - lo_of(h0), v.y - hi_of(h0));
                Bl[row * SROW + c4 * 2 + 1] = bfpack(v.z - lo_of(h1), v.w - hi_of(h1));
            }
        }
        __syncthreads();

#pragma unroll
        for (int ks = 0; ks < 2; ks++) {
            uint32_t bh[4][2], bl[4][2];
#pragma unroll
            for (int nt = 0; nt < 4; nt++) {
                int n = wn * 32 + nt * 8 + g;
                int w = n * SROW + ks * 8 + t;
                bh[nt][0] = Bh[w]; bh[nt][1] = Bh[w + 4];
                bl[nt][0] = Bl[w]; bl[nt][1] = Bl[w + 4];
            }
#pragma unroll
            for (int mt = 0; mt < 4; mt++) {
                int r = wm * 64 + mt * 16 + g;
                int w = r * SROW + ks * 8 + t;
                uint32_t ah[4] = { Ah[w], Ah[w + 8 * SROW], Ah[w + 4], Ah[w + 8 * SROW + 4] };
                uint32_t al[4] = { Al[w], Al[w + 8 * SROW], Al[w + 4], Al[w + 8 * SROW + 4] };
#pragma unroll
                for (int nt = 0; nt < 4; nt++) {
                    mma16816(c[mt][nt], ah, bh[nt]);
                    mma16816(c[mt][nt], al, bh[nt]);
                    mma16816(c[mt][nt], ah, bl[nt]);
                }
            }
        }
    }

#pragma unroll
    for (int mt = 0; mt < 4; mt++) {
#pragma unroll
        for (int nt = 0; nt < 4; nt++) {
            int row = m0 + wm * 64 + mt * 16 + g;
            int col = n0 + wn * 32 + nt * 8 + t * 2;
            *(float2*)&C[(long)row * DM + col]       = make_float2(c[mt][nt][0], c[mt][nt][1]);
            *(float2*)&C[(long)(row + 8) * DM + col] = make_float2(c[mt][nt][2], c[mt][nt][3]);
        }
    }
}

// ============================================================================
// Flash attention on mma.sync bf16 (2-term split both sides).
// BQ=128, BK=64. 8 warps, each warp owns 16 query rows (full 64 keys, full dk).
// grid = (SEQ/128, NH, BATCH), 256 threads.
// ============================================================================
#define VS 36   // smem row stride in u32 words (32 data + 4 pad) -> conflict-free frags

__global__ __launch_bounds__(256) void flash_mma()
{
    __shared__ uint32_t Kh[64*VS], Kl[64*VS], Vh[64*VS], Vl[64*VS];

    const int tid  = threadIdx.x;
    const int warp = tid >> 5, lane = tid & 31;
    const int g = lane >> 2, t = lane & 3;
    const int qb = blockIdx.x, h = blockIdx.y, b = blockIdx.z;
    const int q0 = qb * 128;
    const int headoff = h * DK;
    const long rowbase = (long)(b * SEQ + q0 + warp * 16);
    const float NEG_INF = __int_as_float(0xff800000);

    // ---- Q fragments (hi/lo), pre-scaled by 1/sqrt(64) ----
    uint32_t qh[4][4], ql[4][4];
#pragma unroll
    for (int ks = 0; ks < 4; ks++) {
#pragma unroll
        for (int idx = 0; idx < 4; idx++) {
            int rr = (idx & 1) ? g + 8 : g;
            int d0 = ks * 16 + ((idx >> 1) ? 2 * t + 8 : 2 * t);
            float2 v = *(const float2*)&g_q[(rowbase + rr) * DM + headoff + d0];
            float x = v.x * 0.125f, y = v.y * 0.125f;
            uint32_t hi = bfpack(x, y);
            qh[ks][idx] = hi;
            ql[ks][idx] = bfpack(x - lo_of(hi), y - hi_of(hi));
        }
    }

    float m[2] = {NEG_INF, NEG_INF}, l[2] = {0.f, 0.f};
    float o[8][4];
#pragma unroll
    for (int dt = 0; dt < 8; dt++)
#pragma unroll
        for (int r = 0; r < 4; r++) o[dt][r] = 0.f;

    const int jmax = 2 * (qb + 1);
    for (int jb = 0; jb < jmax; jb++) {
        __syncthreads();
        // ---- load K [key][d] and V^T [d][key] tiles, bf16 hi/lo ----
#pragma unroll
        for (int u = 0; u < 4; u++) {
            int lin = tid + u * 256;       // 1024 = 64 rows x 16 float4
            int r  = lin >> 4;             // key row
            int c4 = lin & 15;             // d float4
            long gaddr = (long)(b * SEQ + jb * 64 + r) * DM + headoff + c4 * 4;
            {
                float4 v = *(const float4*)&g_k[gaddr];
                uint32_t h0 = bfpack(v.x, v.y), h1 = bfpack(v.z, v.w);
                Kh[r * VS + c4 * 2]     = h0;
                Kh[r * VS + c4 * 2 + 1] = h1;
                Kl[r * VS + c4 * 2]     = bfpack(v.x - lo_of(h0), v.y - hi_of(h0));
                Kl[r * VS + c4 * 2 + 1] = bfpack(v.z - lo_of(h1), v.w - hi_of(h1));
            }
            {
                float4 v = *(const float4*)&g_v[gaddr];
                float f[4] = {v.x, v.y, v.z, v.w};
#pragma unroll
                for (int i = 0; i < 4; i++) {
                    uint16_t hb = bf1(f[i]);
                    ((uint16_t*)Vh)[(c4 * 4 + i) * (2 * VS) + r] = hb;
                    ((uint16_t*)Vl)[(c4 * 4 + i) * (2 * VS) + r] = bf1(f[i] - bf1v(hb));
                }
            }
        }
        __syncthreads();

        // ---- S = Q K^T (warp: 16 x 64), fp32 accum ----
        float s[8][4];
#pragma unroll
        for (int nt = 0; nt < 8; nt++)
#pragma unroll
            for (int r = 0; r < 4; r++) s[nt][r] = 0.f;
#pragma unroll
        for (int ks = 0; ks < 4; ks++) {
#pragma unroll
            for (int nt = 0; nt < 8; nt++) {
                int w = (nt * 8 + g) * VS + ks * 8 + t;
                uint32_t bh[2] = {Kh[w], Kh[w + 4]};
                uint32_t bl[2] = {Kl[w], Kl[w + 4]};
                mma16816(s[nt], qh[ks], bh);
                mma16816(s[nt], ql[ks], bh);
                mma16816(s[nt], qh[ks], bl);
            }
        }

        // ---- causal mask (only near-diagonal blocks) ----
        if (jb >= 2 * qb) {
#pragma unroll
            for (int nt = 0; nt < 8; nt++)
#pragma unroll
                for (int r = 0; r < 4; r++) {
                    int key = jb * 64 + nt * 8 + 2 * t + (r & 1);
                    int qr  = q0 + warp * 16 + g + ((r >> 1) ? 8 : 0);
                    if (key > qr) s[nt][r] = NEG_INF;
                }
        }

        // ---- online softmax (rows g and g+8; lanes t share a row) ----
        float mx0 = NEG_INF, mx1 = NEG_INF;
#pragma unroll
        for (int nt = 0; nt < 8; nt++) {
            mx0 = fmaxf(mx0, fmaxf(s[nt][0], s[nt][1]));
            mx1 = fmaxf(mx1, fmaxf(s[nt][2], s[nt][3]));
        }
        mx0 = fmaxf(mx0, __shfl_xor_sync(0xffffffffu, mx0, 1));
        mx0 = fmaxf(mx0, __shfl_xor_sync(0xffffffffu, mx0, 2));
        mx1 = fmaxf(mx1, __shfl_xor_sync(0xffffffffu, mx1, 1));
        mx1 = fmaxf(mx1, __shfl_xor_sync(0xffffffffu, mx1, 2));
        float mn0 = fmaxf(m[0], mx0), mn1 = fmaxf(m[1], mx1);
        float al0 = __expf(m[0] - mn0), al1 = __expf(m[1] - mn1);
        m[0] = mn0; m[1] = mn1;
        float ps0 = 0.f, ps1 = 0.f;
#pragma unroll
        for (int nt = 0; nt < 8; nt++) {
            s[nt][0] = __expf(s[nt][0] - mn0); ps0 += s[nt][0];
            s[nt][1] = __expf(s[nt][1] - mn0); ps0 += s[nt][1];
            s[nt][2] = __expf(s[nt][2] - mn1); ps1 += s[nt][2];
            s[nt][3] = __expf(s[nt][3] - mn1); ps1 += s[nt][3];
        }
        ps0 += __shfl_xor_sync(0xffffffffu, ps0, 1);
        ps0 += __shfl_xor_sync(0xffffffffu, ps0, 2);
        ps1 += __shfl_xor_sync(0xffffffffu, ps1, 1);
        ps1 += __shfl_xor_sync(0xffffffffu, ps1, 2);
        l[0] = l[0] * al0 + ps0;
        l[1] = l[1] * al1 + ps1;
#pragma unroll
        for (int dt = 0; dt < 8; dt++) {
            o[dt][0] *= al0; o[dt][1] *= al0;
            o[dt][2] *= al1; o[dt][3] *= al1;
        }

        // ---- O += P V (P fragments straight from S fragments) ----
#pragma unroll
        for (int kt = 0; kt < 4; kt++) {
            uint32_t ph[4], pl[4];
            ph[0] = bfpack(s[2*kt][0],   s[2*kt][1]);
            ph[1] = bfpack(s[2*kt][2],   s[2*kt][3]);
            ph[2] = bfpack(s[2*kt+1][0], s[2*kt+1][1]);
            ph[3] = bfpack(s[2*kt+1][2], s[2*kt+1][3]);
            pl[0] = bfpack(s[2*kt][0]   - lo_of(ph[0]), s[2*kt][1]   - hi_of(ph[0]));
            pl[1] = bfpack(s[2*kt][2]   - lo_of(ph[1]), s[2*kt][3]   - hi_of(ph[1]));
            pl[2] = bfpack(s[2*kt+1][0] - lo_of(ph[2]), s[2*kt+1][1] - hi_of(ph[2]));
            pl[3] = bfpack(s[2*kt+1][2] - lo_of(ph[3]), s[2*kt+1][3] - hi_of(ph[3]));
#pragma unroll
            for (int dt = 0; dt < 8; dt++) {
                int w = (dt * 8 + g) * VS + kt * 8 + t;
                uint32_t bh[2] = {Vh[w], Vh[w + 4]};
                uint32_t bl[2] = {Vl[w], Vl[w + 4]};
                mma16816(o[dt], ph, bh);
                mma16816(o[dt], pl, bh);
                mma16816(o[dt], ph, bl);
            }
        }
    }

    // ---- epilogue ----
    float inv0 = 1.f / l[0], inv1 = 1.f / l[1];
#pragma unroll
    for (int dt = 0; dt < 8; dt++) {
        int col = headoff + dt * 8 + 2 * t;
        *(float2*)&g_a[(rowbase + g) * DM + col] =
            make_float2(o[dt][0] * inv0, o[dt][1] * inv0);
        *(float2*)&g_a[(rowbase + g + 8) * DM + col] =
            make_float2(o[dt][2] * inv1, o[dt][3] * inv1);
    }
}

// ---------------------------------------------------------------------------
extern "C" void kernel_launch(void* const* d_in, const int* in_sizes, int n_in,
                              void* d_out, int out_size)
{
    const float* x  = (const float*)d_in[0];
    const float* wq = (const float*)d_in[1];
    const float* wk = (const float*)d_in[2];
    const float* wv = (const float*)d_in[3];
    const float* wo = (const float*)d_in[4];
    float* out = (float*)d_out;

    float *q, *k, *v, *a;
    cudaGetSymbolAddress((void**)&q, g_q);
    cudaGetSymbolAddress((void**)&k, g_k);
    cudaGetSymbolAddress((void**)&v, g_v);
    cudaGetSymbolAddress((void**)&a, g_a);

    dim3 gg(DM / 128, MROWS / 128);  // (6, 32)
    gemm_mma<<<gg, 256>>>(x, wq, q);
    gemm_mma<<<gg, 256>>>(x, wk, k);
    gemm_mma<<<gg, 256>>>(x, wv, v);

    flash_mma<<<dim3(SEQ/128, NH, BATCH), 256>>>();

    gemm_mma<<<gg, 256>>>(a, wo, out);
}

// round 8
// speedup vs baseline: 3.0605x; 1.3231x over previous
#include <cuda_runtime.h>
#include <cstdint>

#define BATCH 2
#define SEQ   2048
#define DM    768
#define NH    12
#define DK    64
#define MROWS (BATCH*SEQ)

// Scratch (allocation-free rule: __device__ globals)
__device__ uint16_t g_qh[MROWS*DM], g_ql[MROWS*DM];   // Q bf16 hi/lo, pre-scaled, [token][d]
__device__ uint16_t g_kh[MROWS*DM], g_kl[MROWS*DM];   // K bf16 hi/lo, [token][d]
__device__ uint16_t g_vth[MROWS*DM], g_vtl[MROWS*DM]; // V^T bf16 hi/lo, [(b,h,dl)][token]
__device__ float g_a[MROWS*DM];                       // attention output fp32

// ============================================================================
// helpers
// ============================================================================
__device__ __forceinline__ uint32_t smem_u32(const void* p) {
    uint32_t a;
    asm("{ .reg .u64 t; cvta.to.shared.u64 t, %1; cvt.u32.u64 %0, t; }" : "=r"(a) : "l"(p));
    return a;
}
// pack two f32 -> bf16x2 (x LOW, y HIGH)
__device__ __forceinline__ uint32_t bfpack(float x, float y) {
    uint32_t r;
    asm("cvt.rn.bf16x2.f32 %0, %1, %2;" : "=r"(r) : "f"(y), "f"(x));
    return r;
}
__device__ __forceinline__ float lo_of(uint32_t p)  { return __uint_as_float(p << 16); }
__device__ __forceinline__ float hi_of(uint32_t p)  { return __uint_as_float(p & 0xffff0000u); }
__device__ __forceinline__ uint16_t bf1(float x) {
    uint16_t u; asm("cvt.rn.bf16.f32 %0, %1;" : "=h"(u) : "f"(x)); return u;
}
__device__ __forceinline__ float bf1v(uint16_t u) { return __uint_as_float(((uint32_t)u) << 16); }

__device__ __forceinline__ void mma16816(float* c, const uint32_t* a, const uint32_t* b) {
    asm volatile(
        "mma.sync.aligned.m16n8k16.row.col.f32.bf16.bf16.f32 "
        "{%0,%1,%2,%3}, {%4,%5,%6,%7}, {%8,%9}, {%0,%1,%2,%3};"
        : "+f"(c[0]), "+f"(c[1]), "+f"(c[2]), "+f"(c[3])
        : "r"(a[0]), "r"(a[1]), "r"(a[2]), "r"(a[3]), "r"(b[0]), "r"(b[1]));
}
#define CP16(dst, src) asm volatile("cp.async.ca.shared.global [%0], [%1], 16;" :: "r"(dst), "l"(src))
#define CP_COMMIT()    asm volatile("cp.async.commit_group;" ::: "memory")
#define CP_WAIT0()     asm volatile("cp.async.wait_group 0;" ::: "memory")

#define SROW 18

// ============================================================================
// Fused QKV projection: z = blockIdx.z picks weight + epilogue format.
//  z=0: Q -> g_qh/g_ql (scaled 0.125);  z=1: K -> g_kh/g_kl;
//  z=2: V -> g_vth/g_vtl (smem-staged transpose to [(b,h,d)][token]).
// ============================================================================
__global__ __launch_bounds__(256, 2) void gemm_qkv(const float* __restrict__ A,
                                                   const float* __restrict__ wq,
                                                   const float* __restrict__ wk,
                                                   const float* __restrict__ wv)
{
    __shared__ __align__(16) uint32_t smu[4*128*SROW];
    uint32_t* Ah = smu;
    uint32_t* Al = smu + 128*SROW;
    uint32_t* Bh = smu + 2*128*SROW;
    uint32_t* Bl = smu + 3*128*SROW;

    const int tid  = threadIdx.x;
    const int warp = tid >> 5, lane = tid & 31;
    const int g = lane >> 2, t = lane & 3;
    const int wm = warp >> 2, wn = warp & 3;
    const int m0 = blockIdx.y * 128, n0 = blockIdx.x * 128;
    const int z = blockIdx.z;
    const float* __restrict__ Bm = (z == 0) ? wq : ((z == 1) ? wk : wv);

    float c[4][4][4];
#pragma unroll
    for (int i = 0; i < 4; i++)
#pragma unroll
        for (int j = 0; j < 4; j++)
#pragma unroll
            for (int r = 0; r < 4; r++) c[i][j][r] = 0.f;

    for (int kc = 0; kc < DM / 32; kc++) {
        __syncthreads();
#pragma unroll
        for (int u = 0; u < 4; u++) {
            int lin = tid + u * 256;
            int row = lin >> 3;
            int c4  = lin & 7;
            {
                float4 v = *(const float4*)&A[(long)(m0 + row) * DM + kc * 32 + c4 * 4];
                uint32_t h0 = bfpack(v.x, v.y), h1 = bfpack(v.z, v.w);
                Ah[row * SROW + c4 * 2]     = h0;
                Ah[row * SROW + c4 * 2 + 1] = h1;
                Al[row * SROW + c4 * 2]     = bfpack(v.x - lo_of(h0), v.y - hi_of(h0));
                Al[row * SROW + c4 * 2 + 1] = bfpack(v.z - lo_of(h1), v.w - hi_of(h1));
            }
            {
                float4 v = *(const float4*)&Bm[(long)(n0 + row) * DM + kc * 32 + c4 * 4];
                uint32_t h0 = bfpack(v.x, v.y), h1 = bfpack(v.z, v.w);
                Bh[row * SROW + c4 * 2]     = h0;
                Bh[row * SROW + c4 * 2 + 1] = h1;
                Bl[row * SROW + c4 * 2]     = bfpack(v.x - lo_of(h0), v.y - hi_of(h0));
                Bl[row * SROW + c4 * 2 + 1] = bfpack(v.z - lo_of(h1), v.w - hi_of(h1));
            }
        }
        __syncthreads();

#pragma unroll
        for (int ks = 0; ks < 2; ks++) {
            uint32_t bh[4][2], bl[4][2];
#pragma unroll
            for (int nt = 0; nt < 4; nt++) {
                int n = wn * 32 + nt * 8 + g;
                int w = n * SROW + ks * 8 + t;
                bh[nt][0] = Bh[w]; bh[nt][1] = Bh[w + 4];
                bl[nt][0] = Bl[w]; bl[nt][1] = Bl[w + 4];
            }
#pragma unroll
            for (int mt = 0; mt < 4; mt++) {
                int r = wm * 64 + mt * 16 + g;
                int w = r * SROW + ks * 8 + t;
                uint32_t ah[4] = { Ah[w], Ah[w + 8 * SROW], Ah[w + 4], Ah[w + 8 * SROW + 4] };
                uint32_t al[4] = { Al[w], Al[w + 8 * SROW], Al[w + 4], Al[w + 8 * SROW + 4] };
#pragma unroll
                for (int nt = 0; nt < 4; nt++) {
                    mma16816(c[mt][nt], ah, bh[nt]);
                    mma16816(c[mt][nt], al, bh[nt]);
                    mma16816(c[mt][nt], ah, bl[nt]);
                }
            }
        }
    }

    // ---- epilogues ----
    if (z < 2) {
        uint16_t* Hh = (z == 0) ? g_qh : g_kh;
        uint16_t* Hl = (z == 0) ? g_ql : g_kl;
        const float sc = (z == 0) ? 0.125f : 1.0f;
#pragma unroll
        for (int mt = 0; mt < 4; mt++) {
#pragma unroll
            for (int nt = 0; nt < 4; nt++) {
                int row = m0 + wm * 64 + mt * 16 + g;
                int col = n0 + wn * 32 + nt * 8 + 2 * t;
                float x0 = c[mt][nt][0] * sc, x1 = c[mt][nt][1] * sc;
                float x2 = c[mt][nt][2] * sc, x3 = c[mt][nt][3] * sc;
                uint32_t h0 = bfpack(x0, x1), h1 = bfpack(x2, x3);
                *(uint32_t*)&Hh[(long)row * DM + col]       = h0;
                *(uint32_t*)&Hl[(long)row * DM + col]       = bfpack(x0 - lo_of(h0), x1 - hi_of(h0));
                *(uint32_t*)&Hh[(long)(row + 8) * DM + col] = h1;
                *(uint32_t*)&Hl[(long)(row + 8) * DM + col] = bfpack(x2 - lo_of(h1), x3 - hi_of(h1));
            }
        }
    } else {
        // V: transpose 128x128 tile via smem, write [(b,h,dl)][token] bf16 hi/lo
        uint16_t* st = (uint16_t*)smu;      // 128 x 136 u16 = 34816 B
        const int b = m0 / SEQ, s0 = m0 % SEQ;
#pragma unroll
        for (int pass = 0; pass < 2; pass++) {
            __syncthreads();
#pragma unroll
            for (int mt = 0; mt < 4; mt++)
#pragma unroll
                for (int nt = 0; nt < 4; nt++)
#pragma unroll
                    for (int r = 0; r < 4; r++) {
                        float cv = c[mt][nt][r];
                        uint16_t hv = bf1(cv);
                        uint16_t val = pass ? bf1(cv - bf1v(hv)) : hv;
                        int rowl = wm * 64 + mt * 16 + g + ((r >> 1) ? 8 : 0);
                        int coll = wn * 32 + nt * 8 + 2 * t + (r & 1);
                        st[coll * 136 + rowl] = val;
                    }
            __syncthreads();
            uint16_t* dstb = pass ? g_vtl : g_vth;
#pragma unroll
            for (int u = 0; u < 8; u++) {
                int idx = tid + u * 256;            // 2048 uint4 chunks
                int dl128 = idx >> 4, ch = idx & 15;
                uint4 v = *(const uint4*)&st[dl128 * 136 + ch * 8];
                int colg = n0 + dl128;
                int hh = colg >> 6, dl = colg & 63;
                *(uint4*)&dstb[((long)((b * NH + hh) * DK + dl)) * SEQ + s0 + ch * 8] = v;
            }
        }
    }
}

// ============================================================================
// Output projection GEMM (fp32 in/out, unchanged numerics)
// ============================================================================
__global__ __launch_bounds__(256, 2) void gemm_mma(const float* __restrict__ A,
                                                   const float* __restrict__ Bm,
                                                   float* __restrict__ C)
{
    __shared__ uint32_t Ah[128*SROW], Al[128*SROW], Bh[128*SROW], Bl[128*SROW];

    const int tid  = threadIdx.x;
    const int warp = tid >> 5, lane = tid & 31;
    const int g = lane >> 2, t = lane & 3;
    const int wm = warp >> 2, wn = warp & 3;
    const int m0 = blockIdx.y * 128, n0 = blockIdx.x * 128;

    float c[4][4][4];
#pragma unroll
    for (int i = 0; i < 4; i++)
#pragma unroll
        for (int j = 0; j < 4; j++)
#pragma unroll
            for (int r = 0; r < 4; r++) c[i][j][r] = 0.f;

    for (int kc = 0; kc < DM / 32; kc++) {
        __syncthreads();
#pragma unroll
        for (int u = 0; u < 4; u++) {
            int lin = tid + u * 256;
            int row = lin >> 3;
            int c4  = lin & 7;
            {
                float4 v = *(const float4*)&A[(long)(m0 + row) * DM + kc * 32 + c4 * 4];
                uint32_t h0 = bfpack(v.x, v.y), h1 = bfpack(v.z, v.w);
                Ah[row * SROW + c4 * 2]     = h0;
                Ah[row * SROW + c4 * 2 + 1] = h1;
                Al[row * SROW + c4 * 2]     = bfpack(v.x - lo_of(h0), v.y - hi_of(h0));
                Al[row * SROW + c4 * 2 + 1] = bfpack(v.z - lo_of(h1), v.w - hi_of(h1));
            }
            {
                float4 v = *(const float4*)&Bm[(long)(n0 + row) * DM + kc * 32 + c4 * 4];
                uint32_t h0 = bfpack(v.x, v.y), h1 = bfpack(v.z, v.w);
                Bh[row * SROW + c4 * 2]     = h0;
                Bh[row * SROW + c4 * 2 + 1] = h1;
                Bl[row * SROW + c4 * 2]     = bfpack(v.x - lo_of(h0), v.y - hi_of(h0));
                Bl[row * SROW + c4 * 2 + 1] = bfpack(v.z - lo_of(h1), v.w - hi_of(h1));
            }
        }
        __syncthreads();

#pragma unroll
        for (int ks = 0; ks < 2; ks++) {
            uint32_t bh[4][2], bl[4][2];
#pragma unroll
            for (int nt = 0; nt < 4; nt++) {
                int n = wn * 32 + nt * 8 + g;
                int w = n * SROW + ks * 8 + t;
                bh[nt][0] = Bh[w]; bh[nt][1] = Bh[w + 4];
                bl[nt][0] = Bl[w]; bl[nt][1] = Bl[w + 4];
            }
#pragma unroll
            for (int mt = 0; mt < 4; mt++) {
                int r = wm * 64 + mt * 16 + g;
                int w = r * SROW + ks * 8 + t;
                uint32_t ah[4] = { Ah[w], Ah[w + 8 * SROW], Ah[w + 4], Ah[w + 8 * SROW + 4] };
                uint32_t al[4] = { Al[w], Al[w + 8 * SROW], Al[w + 4], Al[w + 8 * SROW + 4] };
#pragma unroll
                for (int nt = 0; nt < 4; nt++) {
                    mma16816(c[mt][nt], ah, bh[nt]);
                    mma16816(c[mt][nt], al, bh[nt]);
                    mma16816(c[mt][nt], ah, bl[nt]);
                }
            }
        }
    }

#pragma unroll
    for (int mt = 0; mt < 4; mt++) {
#pragma unroll
        for (int nt = 0; nt < 4; nt++) {
            int row = m0 + wm * 64 + mt * 16 + g;
            int col = n0 + wn * 32 + nt * 8 + t * 2;
            *(float2*)&C[(long)row * DM + col]       = make_float2(c[mt][nt][0], c[mt][nt][1]);
            *(float2*)&C[(long)(row + 8) * DM + col] = make_float2(c[mt][nt][2], c[mt][nt][3]);
        }
    }
}

// ============================================================================
// Flash attention: pre-converted bf16 inputs, cp.async double-buffered K/V.
// BQ=128, BK=64, 8 warps x 16 q-rows. grid = (SEQ/128, NH, BATCH).
// ============================================================================
#define VS 36                           // smem row stride (u32)
#define ARR_U32 (64*VS)                 // 2304 u32 per array
#define STAGE_U32 (4*ARR_U32)           // 9216 u32 per stage
#define FL_SMEM (2*STAGE_U32*4)         // 73728 B

__global__ __launch_bounds__(256) void flash_mma()
{
    extern __shared__ __align__(16) uint32_t fsm[];
    const uint32_t smb = smem_u32(fsm);

    const int tid  = threadIdx.x;
    const int warp = tid >> 5, lane = tid & 31;
    const int g = lane >> 2, t = lane & 3;
    const int qb = blockIdx.x, h = blockIdx.y, b = blockIdx.z;
    const int q0 = qb * 128;
    const int headoff = h * DK;
    const long rowbase = (long)(b * SEQ + q0 + warp * 16);
    const long vtbase  = (long)((b * NH + h) * DK) * SEQ;
    const float NEG_INF = __int_as_float(0xff800000);

    // ---- Q fragments (already scaled + split) ----
    uint32_t qh[4][4], ql[4][4];
#pragma unroll
    for (int ks = 0; ks < 4; ks++) {
#pragma unroll
        for (int idx = 0; idx < 4; idx++) {
            int rr = (idx & 1) ? g + 8 : g;
            int d0 = ks * 16 + ((idx >> 1) ? 2 * t + 8 : 2 * t);
            long off = (rowbase + rr) * DM + headoff + d0;
            qh[ks][idx] = *(const uint32_t*)&g_qh[off];
            ql[ks][idx] = *(const uint32_t*)&g_ql[off];
        }
    }

    float m[2] = {NEG_INF, NEG_INF}, l[2] = {0.f, 0.f};
    float o[8][4];
#pragma unroll
    for (int dt = 0; dt < 8; dt++)
#pragma unroll
        for (int r = 0; r < 4; r++) o[dt][r] = 0.f;

    const int jmax = 2 * (qb + 1);

    // prefetch helper: 2048 x 16B chunks (4 arrays x 64 rows x 8 chunks)
    auto prefetch = [&](int jb, int stg) {
        const int row = ((tid >> 3) & 31);      // base row component from tid
        const int ch  = tid & 7;
#pragma unroll
        for (int u = 0; u < 8; u++) {
            int arr = u >> 1;                   // exact: lin = tid + u*256
            int r2  = ((u & 1) << 5) + (tid >> 3);
            const uint16_t* src;
            long koff = (long)(b * SEQ + jb * 64 + r2) * DM + headoff + ch * 8;
            long voff = vtbase + (long)r2 * SEQ + jb * 64 + ch * 8;
            if      (arr == 0) src = g_kh  + koff;
            else if (arr == 1) src = g_kl  + koff;
            else if (arr == 2) src = g_vth + voff;
            else               src = g_vtl + voff;
            uint32_t dst = smb + (uint32_t)(stg * STAGE_U32 + arr * ARR_U32 + r2 * VS) * 4 + ch * 16;
            CP16(dst, src);
        }
        CP_COMMIT();
        (void)row;
    };

    prefetch(0, 0);

    for (int jb = 0; jb < jmax; jb++) {
        const int stg = jb & 1;
        CP_WAIT0();
        __syncthreads();
        if (jb + 1 < jmax) prefetch(jb + 1, stg ^ 1);

        const uint32_t* Kh = fsm + stg * STAGE_U32;
        const uint32_t* Kl = Kh + ARR_U32;
        const uint32_t* Vh = Kh + 2 * ARR_U32;
        const uint32_t* Vl = Kh + 3 * ARR_U32;

        // ---- S = Q K^T ----
        float s[8][4];
#pragma unroll
        for (int nt = 0; nt < 8; nt++)
#pragma unroll
            for (int r = 0; r < 4; r++) s[nt][r] = 0.f;
#pragma unroll
        for (int ks = 0; ks < 4; ks++) {
#pragma unroll
            for (int nt = 0; nt < 8; nt++) {
                int w = (nt * 8 + g) * VS + ks * 8 + t;
                uint32_t bh[2] = {Kh[w], Kh[w + 4]};
                uint32_t bl[2] = {Kl[w], Kl[w + 4]};
                mma16816(s[nt], qh[ks], bh);
                mma16816(s[nt], ql[ks], bh);
                mma16816(s[nt], qh[ks], bl);
            }
        }

        // ---- causal mask ----
        if (jb >= 2 * qb) {
#pragma unroll
            for (int nt = 0; nt < 8; nt++)
#pragma unroll
                for (int r = 0; r < 4; r++) {
                    int key = jb * 64 + nt * 8 + 2 * t + (r & 1);
                    int qr  = q0 + warp * 16 + g + ((r >> 1) ? 8 : 0);
                    if (key > qr) s[nt][r] = NEG_INF;
                }
        }

        // ---- online softmax ----
        float mx0 = NEG_INF, mx1 = NEG_INF;
#pragma unroll
        for (int nt = 0; nt < 8; nt++) {
            mx0 = fmaxf(mx0, fmaxf(s[nt][0], s[nt][1]));
            mx1 = fmaxf(mx1, fmaxf(s[nt][2], s[nt][3]));
        }
        mx0 = fmaxf(mx0, __shfl_xor_sync(0xffffffffu, mx0, 1));
        mx0 = fmaxf(mx0, __shfl_xor_sync(0xffffffffu, mx0, 2));
        mx1 = fmaxf(mx1, __shfl_xor_sync(0xffffffffu, mx1, 1));
        mx1 = fmaxf(mx1, __shfl_xor_sync(0xffffffffu, mx1, 2));
        float mn0 = fmaxf(m[0], mx0), mn1 = fmaxf(m[1], mx1);
        float al0 = __expf(m[0] - mn0), al1 = __expf(m[1] - mn1);
        m[0] = mn0; m[1] = mn1;
        float ps0 = 0.f, ps1 = 0.f;
#pragma unroll
        for (int nt = 0; nt < 8; nt++) {
            s[nt][0] = __expf(s[nt][0] - mn0); ps0 += s[nt][0];
            s[nt][1] = __expf(s[nt][1] - mn0); ps0 += s[nt][1];
            s[nt][2] = __expf(s[nt][2] - mn1); ps1 += s[nt][2];
            s[nt][3] = __expf(s[nt][3] - mn1); ps1 += s[nt][3];
        }
        ps0 += __shfl_xor_sync(0xffffffffu, ps0, 1);
        ps0 += __shfl_xor_sync(0xffffffffu, ps0, 2);
        ps1 += __shfl_xor_sync(0xffffffffu, ps1, 1);
        ps1 += __shfl_xor_sync(0xffffffffu, ps1, 2);
        l[0] = l[0] * al0 + ps0;
        l[1] = l[1] * al1 + ps1;
#pragma unroll
        for (int dt = 0; dt < 8; dt++) {
            o[dt][0] *= al0; o[dt][1] *= al0;
            o[dt][2] *= al1; o[dt][3] *= al1;
        }

        // ---- O += P V ----
#pragma unroll
        for (int kt = 0; kt < 4; kt++) {
            uint32_t ph[4], pl[4];
            ph[0] = bfpack(s[2*kt][0],   s[2*kt][1]);
            ph[1] = bfpack(s[2*kt][2],   s[2*kt][3]);
            ph[2] = bfpack(s[2*kt+1][0], s[2*kt+1][1]);
            ph[3] = bfpack(s[2*kt+1][2], s[2*kt+1][3]);
            pl[0] = bfpack(s[2*kt][0]   - lo_of(ph[0]), s[2*kt][1]   - hi_of(ph[0]));
            pl[1] = bfpack(s[2*kt][2]   - lo_of(ph[1]), s[2*kt][3]   - hi_of(ph[1]));
            pl[2] = bfpack(s[2*kt+1][0] - lo_of(ph[2]), s[2*kt+1][1] - hi_of(ph[2]));
            pl[3] = bfpack(s[2*kt+1][2] - lo_of(ph[3]), s[2*kt+1][3] - hi_of(ph[3]));
#pragma unroll
            for (int dt = 0; dt < 8; dt++) {
                int w = (dt * 8 + g) * VS + kt * 8 + t;
                uint32_t bh[2] = {Vh[w], Vh[w + 4]};
                uint32_t bl[2] = {Vl[w], Vl[w + 4]};
                mma16816(o[dt], ph, bh);
                mma16816(o[dt], pl, bh);
                mma16816(o[dt], ph, bl);
            }
        }
    }

    // ---- epilogue ----
    float inv0 = 1.f / l[0], inv1 = 1.f / l[1];
#pragma unroll
    for (int dt = 0; dt < 8; dt++) {
        int col = headoff + dt * 8 + 2 * t;
        *(float2*)&g_a[(rowbase + g) * DM + col] =
            make_float2(o[dt][0] * inv0, o[dt][1] * inv0);
        *(float2*)&g_a[(rowbase + g + 8) * DM + col] =
            make_float2(o[dt][2] * inv1, o[dt][3] * inv1);
    }
}

// ---------------------------------------------------------------------------
extern "C" void kernel_launch(void* const* d_in, const int* in_sizes, int n_in,
                              void* d_out, int out_size)
{
    const float* x  = (const float*)d_in[0];
    const float* wq = (const float*)d_in[1];
    const float* wk = (const float*)d_in[2];
    const float* wv = (const float*)d_in[3];
    const float* wo = (const float*)d_in[4];
    float* out = (float*)d_out;

    float* a;
    cudaGetSymbolAddress((void**)&a, g_a);

    cudaFuncSetAttribute(flash_mma, cudaFuncAttributeMaxDynamicSharedMemorySize, FL_SMEM);

    gemm_qkv<<<dim3(DM / 128, MROWS / 128, 3), 256>>>(x, wq, wk, wv);
    flash_mma<<<dim3(SEQ / 128, NH, BATCH), 256, FL_SMEM>>>();
    gemm_mma<<<dim3(DM / 128, MROWS / 128), 256>>>(a, wo, out);
}

// round 10
// speedup vs baseline: 3.5704x; 1.1666x over previous
#include <cuda_runtime.h>
#include <cstdint>

#define BATCH 2
#define SEQ   2048
#define DM    768
#define NH    12
#define DK    64
#define MROWS (BATCH*SEQ)

// Scratch (allocation-free rule: __device__ globals)
__device__ uint16_t g_qh[MROWS*DM], g_ql[MROWS*DM];   // Q bf16 hi/lo, pre-scaled, [token][d]
__device__ uint16_t g_kh[MROWS*DM], g_kl[MROWS*DM];   // K bf16 hi/lo, [token][d]
__device__ uint16_t g_vth[MROWS*DM], g_vtl[MROWS*DM]; // V^T bf16 hi/lo, [(b,h,dl)][token]
__device__ float g_a[MROWS*DM];                       // attention output fp32

// ============================================================================
// helpers
// ============================================================================
__device__ __forceinline__ uint32_t smem_u32(const void* p) {
    uint32_t a;
    asm("{ .reg .u64 t; cvta.to.shared.u64 t, %1; cvt.u32.u64 %0, t; }" : "=r"(a) : "l"(p));
    return a;
}
__device__ __forceinline__ uint32_t bfpack(float x, float y) {
    uint32_t r;
    asm("cvt.rn.bf16x2.f32 %0, %1, %2;" : "=r"(r) : "f"(y), "f"(x));
    return r;
}
__device__ __forceinline__ float lo_of(uint32_t p)  { return __uint_as_float(p << 16); }
__device__ __forceinline__ float hi_of(uint32_t p)  { return __uint_as_float(p & 0xffff0000u); }
__device__ __forceinline__ uint16_t bf1(float x) {
    uint16_t u; asm("cvt.rn.bf16.f32 %0, %1;" : "=h"(u) : "f"(x)); return u;
}
__device__ __forceinline__ float bf1v(uint16_t u) { return __uint_as_float(((uint32_t)u) << 16); }

__device__ __forceinline__ void mma16816(float* c, const uint32_t* a, const uint32_t* b) {
    asm volatile(
        "mma.sync.aligned.m16n8k16.row.col.f32.bf16.bf16.f32 "
        "{%0,%1,%2,%3}, {%4,%5,%6,%7}, {%8,%9}, {%0,%1,%2,%3};"
        : "+f"(c[0]), "+f"(c[1]), "+f"(c[2]), "+f"(c[3])
        : "r"(a[0]), "r"(a[1]), "r"(a[2]), "r"(a[3]), "r"(b[0]), "r"(b[1]));
}
__device__ __forceinline__ void ldsm4(uint32_t* r, uint32_t addr) {
    asm volatile("ldmatrix.sync.aligned.m8n8.x4.shared.b16 {%0,%1,%2,%3}, [%4];"
        : "=r"(r[0]), "=r"(r[1]), "=r"(r[2]), "=r"(r[3]) : "r"(addr));
}
#define CP16(dst, src) asm volatile("cp.async.ca.shared.global [%0], [%1], 16;" :: "r"(dst), "l"(src))
#define CP_COMMIT()    asm volatile("cp.async.commit_group;" ::: "memory")
#define CP_WAIT0()     asm volatile("cp.async.wait_group 0;" ::: "memory")

#define SROW 20   // GEMM smem row stride (u32): 16 data + 4 pad, LDSM conflict-free

// ============================================================================
// Shared GEMM mainloop body (A/W fp32 -> bf16 hi/lo smem -> LDSM -> 3x mma)
// Computes c[4][4][4] for a 128x128 tile at (m0, n0).
// ============================================================================
__device__ __forceinline__ void gemm_core(const float* __restrict__ A,
                                          const float* __restrict__ Bm,
                                          uint32_t* Ah, uint32_t* Al,
                                          uint32_t* Bh, uint32_t* Bl,
                                          int m0, int n0, int tid, float c[4][4][4])
{
    const int warp = tid >> 5, lane = tid & 31;
    const int wm = warp >> 2, wn = warp & 3;
    const uint32_t sAh = smem_u32(Ah), sAl = smem_u32(Al);
    const uint32_t sBh = smem_u32(Bh), sBl = smem_u32(Bl);

    // LDSM lane address components (word offsets)
    const int a_row = (lane & 15);
    const int a_hk  = (lane >> 4) * 4;
    const int b_row = ((lane >> 4) << 3) + (lane & 7);
    const int b_hk  = ((lane >> 3) & 1) * 4;

    for (int kc = 0; kc < DM / 32; kc++) {
        __syncthreads();
#pragma unroll
        for (int u = 0; u < 4; u++) {
            int lin = tid + u * 256;
            int row = lin >> 3;
            int c4  = lin & 7;
            {
                float4 v = *(const float4*)&A[(long)(m0 + row) * DM + kc * 32 + c4 * 4];
                uint32_t h0 = bfpack(v.x, v.y), h1 = bfpack(v.z, v.w);
                *(uint2*)&Ah[row * SROW + c4 * 2] = make_uint2(h0, h1);
                *(uint2*)&Al[row * SROW + c4 * 2] = make_uint2(
                    bfpack(v.x - lo_of(h0), v.y - hi_of(h0)),
                    bfpack(v.z - lo_of(h1), v.w - hi_of(h1)));
            }
            {
                float4 v = *(const float4*)&Bm[(long)(n0 + row) * DM + kc * 32 + c4 * 4];
                uint32_t h0 = bfpack(v.x, v.y), h1 = bfpack(v.z, v.w);
                *(uint2*)&Bh[row * SROW + c4 * 2] = make_uint2(h0, h1);
                *(uint2*)&Bl[row * SROW + c4 * 2] = make_uint2(
                    bfpack(v.x - lo_of(h0), v.y - hi_of(h0)),
                    bfpack(v.z - lo_of(h1), v.w - hi_of(h1)));
            }
        }
        __syncthreads();

#pragma unroll
        for (int ks = 0; ks < 2; ks++) {
            uint32_t bh[4][2], bl[4][2];
#pragma unroll
            for (int p = 0; p < 2; p++) {
                uint32_t off = (uint32_t)((wn * 32 + p * 16 + b_row) * SROW + ks * 8 + b_hk) * 4;
                uint32_t rr[4];
                ldsm4(rr, sBh + off);
                bh[2*p][0] = rr[0]; bh[2*p][1] = rr[1];
                bh[2*p+1][0] = rr[2]; bh[2*p+1][1] = rr[3];
                ldsm4(rr, sBl + off);
                bl[2*p][0] = rr[0]; bl[2*p][1] = rr[1];
                bl[2*p+1][0] = rr[2]; bl[2*p+1][1] = rr[3];
            }
#pragma unroll
            for (int mt = 0; mt < 4; mt++) {
                uint32_t off = (uint32_t)((wm * 64 + mt * 16 + a_row) * SROW + ks * 8 + a_hk) * 4;
                uint32_t ah[4], al[4];
                ldsm4(ah, sAh + off);
                ldsm4(al, sAl + off);
#pragma unroll
                for (int nt = 0; nt < 4; nt++) {
                    mma16816(c[mt][nt], ah, bh[nt]);
                    mma16816(c[mt][nt], al, bh[nt]);
                    mma16816(c[mt][nt], ah, bl[nt]);
                }
            }
        }
    }
}

// ============================================================================
// Fused QKV projection (z picks weight + epilogue)
// ============================================================================
__global__ __launch_bounds__(256, 2) void gemm_qkv(const float* __restrict__ A,
                                                   const float* __restrict__ wq,
                                                   const float* __restrict__ wk,
                                                   const float* __restrict__ wv)
{
    __shared__ __align__(16) uint32_t smu[4*128*SROW];
    uint32_t* Ah = smu;
    uint32_t* Al = smu + 128*SROW;
    uint32_t* Bh = smu + 2*128*SROW;
    uint32_t* Bl = smu + 3*128*SROW;

    const int tid  = threadIdx.x;
    const int warp = tid >> 5, lane = tid & 31;
    const int g = lane >> 2, t = lane & 3;
    const int wm = warp >> 2, wn = warp & 3;
    const int m0 = blockIdx.y * 128, n0 = blockIdx.x * 128;
    const int z = blockIdx.z;
    const float* __restrict__ Bm = (z == 0) ? wq : ((z == 1) ? wk : wv);

    float c[4][4][4];
#pragma unroll
    for (int i = 0; i < 4; i++)
#pragma unroll
        for (int j = 0; j < 4; j++)
#pragma unroll
            for (int r = 0; r < 4; r++) c[i][j][r] = 0.f;

    gemm_core(A, Bm, Ah, Al, Bh, Bl, m0, n0, tid, c);

    if (z < 2) {
        uint16_t* Hh = (z == 0) ? g_qh : g_kh;
        uint16_t* Hl = (z == 0) ? g_ql : g_kl;
        const float sc = (z == 0) ? 0.125f : 1.0f;
#pragma unroll
        for (int mt = 0; mt < 4; mt++) {
#pragma unroll
            for (int nt = 0; nt < 4; nt++) {
                int row = m0 + wm * 64 + mt * 16 + g;
                int col = n0 + wn * 32 + nt * 8 + 2 * t;
                float x0 = c[mt][nt][0] * sc, x1 = c[mt][nt][1] * sc;
                float x2 = c[mt][nt][2] * sc, x3 = c[mt][nt][3] * sc;
                uint32_t h0 = bfpack(x0, x1), h1 = bfpack(x2, x3);
                *(uint32_t*)&Hh[(long)row * DM + col]       = h0;
                *(uint32_t*)&Hl[(long)row * DM + col]       = bfpack(x0 - lo_of(h0), x1 - hi_of(h0));
                *(uint32_t*)&Hh[(long)(row + 8) * DM + col] = h1;
                *(uint32_t*)&Hl[(long)(row + 8) * DM + col] = bfpack(x2 - lo_of(h1), x3 - hi_of(h1));
            }
        }
    } else {
        // V: transpose 128x128 tile via smem, write [(b,h,dl)][token] bf16 hi/lo
        uint16_t* st = (uint16_t*)smu;      // 128 x 136 u16 = 34816 B (< 40960)
        const int b = m0 / SEQ, s0 = m0 % SEQ;
#pragma unroll
        for (int pass = 0; pass < 2; pass++) {
            __syncthreads();
#pragma unroll
            for (int mt = 0; mt < 4; mt++)
#pragma unroll
                for (int nt = 0; nt < 4; nt++)
#pragma unroll
                    for (int r = 0; r < 4; r++) {
                        float cv = c[mt][nt][r];
                        uint16_t hv = bf1(cv);
                        uint16_t val = pass ? bf1(cv - bf1v(hv)) : hv;
                        int rowl = wm * 64 + mt * 16 + g + ((r >> 1) ? 8 : 0);
                        int coll = wn * 32 + nt * 8 + 2 * t + (r & 1);
                        st[coll * 136 + rowl] = val;
                    }
            __syncthreads();
            uint16_t* dstb = pass ? g_vtl : g_vth;
#pragma unroll
            for (int u = 0; u < 8; u++) {
                int idx = tid + u * 256;
                int dl128 = idx >> 4, ch = idx & 15;
                uint4 v = *(const uint4*)&st[dl128 * 136 + ch * 8];
                int colg = n0 + dl128;
                int hh = colg >> 6, dl = colg & 63;
                *(uint4*)&dstb[((long)((b * NH + hh) * DK + dl)) * SEQ + s0 + ch * 8] = v;
            }
        }
    }
}

// ============================================================================
// Output projection GEMM (fp32 out)
// ============================================================================
__global__ __launch_bounds__(256, 2) void gemm_mma(const float* __restrict__ A,
                                                   const float* __restrict__ Bm,
                                                   float* __restrict__ C)
{
    __shared__ __align__(16) uint32_t smu[4*128*SROW];
    uint32_t* Ah = smu;
    uint32_t* Al = smu + 128*SROW;
    uint32_t* Bh = smu + 2*128*SROW;
    uint32_t* Bl = smu + 3*128*SROW;

    const int tid  = threadIdx.x;
    const int warp = tid >> 5, lane = tid & 31;
    const int g = lane >> 2, t = lane & 3;
    const int wm = warp >> 2, wn = warp & 3;
    const int m0 = blockIdx.y * 128, n0 = blockIdx.x * 128;

    float c[4][4][4];
#pragma unroll
    for (int i = 0; i < 4; i++)
#pragma unroll
        for (int j = 0; j < 4; j++)
#pragma unroll
            for (int r = 0; r < 4; r++) c[i][j][r] = 0.f;

    gemm_core(A, Bm, Ah, Al, Bh, Bl, m0, n0, tid, c);

#pragma unroll
    for (int mt = 0; mt < 4; mt++) {
#pragma unroll
        for (int nt = 0; nt < 4; nt++) {
            int row = m0 + wm * 64 + mt * 16 + g;
            int col = n0 + wn * 32 + nt * 8 + t * 2;
            *(float2*)&C[(long)row * DM + col]       = make_float2(c[mt][nt][0], c[mt][nt][1]);
            *(float2*)&C[(long)(row + 8) * DM + col] = make_float2(c[mt][nt][2], c[mt][nt][3]);
        }
    }
}

// ============================================================================
// Flash attention: pre-converted bf16 inputs, cp.async double-buffered K/V,
// LDSM fragment loads. BQ=128, BK=64. grid = (SEQ/128, NH, BATCH).
// ============================================================================
#define VS 36                           // smem row stride (u32): 32 data + 4 pad, LDSM conflict-free
#define ARR_U32 (64*VS)
#define STAGE_U32 (4*ARR_U32)
#define FL_SMEM (2*STAGE_U32*4)         // 73728 B

__global__ __launch_bounds__(256) void flash_mma()
{
    extern __shared__ __align__(16) uint32_t fsm[];
    const uint32_t smb = smem_u32(fsm);

    const int tid  = threadIdx.x;
    const int warp = tid >> 5, lane = tid & 31;
    const int g = lane >> 2, t = lane & 3;
    const int qb = blockIdx.x, h = blockIdx.y, b = blockIdx.z;
    const int q0 = qb * 128;
    const int headoff = h * DK;
    const long rowbase = (long)(b * SEQ + q0 + warp * 16);
    const long vtbase  = (long)((b * NH + h) * DK) * SEQ;
    const float NEG_INF = __int_as_float(0xff800000);

    // LDSM lane address components (B-style fragments for K and V^T)
    const int f_row = ((lane >> 4) << 3) + (lane & 7);
    const int f_hk  = ((lane >> 3) & 1) * 4;

    // ---- Q fragments (already scaled + split) ----
    uint32_t qh[4][4], ql[4][4];
#pragma unroll
    for (int ks = 0; ks < 4; ks++) {
#pragma unroll
        for (int idx = 0; idx < 4; idx++) {
            int rr = (idx & 1) ? g + 8 : g;
            int d0 = ks * 16 + ((idx >> 1) ? 2 * t + 8 : 2 * t);
            long off = (rowbase + rr) * DM + headoff + d0;
            qh[ks][idx] = *(const uint32_t*)&g_qh[off];
            ql[ks][idx] = *(const uint32_t*)&g_ql[off];
        }
    }

    float m[2] = {NEG_INF, NEG_INF}, l[2] = {0.f, 0.f};
    float o[8][4];
#pragma unroll
    for (int dt = 0; dt < 8; dt++)
#pragma unroll
        for (int r = 0; r < 4; r++) o[dt][r] = 0.f;

    const int jmax = 2 * (qb + 1);

    auto prefetch = [&](int jb, int stg) {
        const int ch = tid & 7;
#pragma unroll
        for (int u = 0; u < 8; u++) {
            int arr = u >> 1;
            int r2  = ((u & 1) << 5) + (tid >> 3);
            const uint16_t* src;
            long koff = (long)(b * SEQ + jb * 64 + r2) * DM + headoff + ch * 8;
            long voff = vtbase + (long)r2 * SEQ + jb * 64 + ch * 8;
            if      (arr == 0) src = g_kh  + koff;
            else if (arr == 1) src = g_kl  + koff;
            else if (arr == 2) src = g_vth + voff;
            else               src = g_vtl + voff;
            uint32_t dst = smb + (uint32_t)(stg * STAGE_U32 + arr * ARR_U32 + r2 * VS) * 4 + ch * 16;
            CP16(dst, src);
        }
        CP_COMMIT();
    };

    prefetch(0, 0);

    for (int jb = 0; jb < jmax; jb++) {
        const int stg = jb & 1;
        CP_WAIT0();
        __syncthreads();
        if (jb + 1 < jmax) prefetch(jb + 1, stg ^ 1);

        const uint32_t sK  = smb + (uint32_t)(stg * STAGE_U32) * 4;
        const uint32_t sKl = sK + ARR_U32 * 4;
        const uint32_t sVh = sK + 2 * ARR_U32 * 4;
        const uint32_t sVl = sK + 3 * ARR_U32 * 4;

        // ---- S = Q K^T ----
        float s[8][4];
#pragma unroll
        for (int nt = 0; nt < 8; nt++)
#pragma unroll
            for (int r = 0; r < 4; r++) s[nt][r] = 0.f;
#pragma unroll
        for (int ks = 0; ks < 4; ks++) {
#pragma unroll
            for (int p = 0; p < 4; p++) {
                uint32_t off = (uint32_t)((p * 16 + f_row) * VS + ks * 8 + f_hk) * 4;
                uint32_t kh[4], kl[4];
                ldsm4(kh, sK  + off);
                ldsm4(kl, sKl + off);
                mma16816(s[2*p],   qh[ks], kh);
                mma16816(s[2*p],   ql[ks], kh);
                mma16816(s[2*p],   qh[ks], kl);
                mma16816(s[2*p+1], qh[ks], kh + 2);
                mma16816(s[2*p+1], ql[ks], kh + 2);
                mma16816(s[2*p+1], qh[ks], kl + 2);
            }
        }

        // ---- causal mask ----
        if (jb >= 2 * qb) {
#pragma unroll
            for (int nt = 0; nt < 8; nt++)
#pragma unroll
                for (int r = 0; r < 4; r++) {
                    int key = jb * 64 + nt * 8 + 2 * t + (r & 1);
                    int qr  = q0 + warp * 16 + g + ((r >> 1) ? 8 : 0);
                    if (key > qr) s[nt][r] = NEG_INF;
                }
        }

        // ---- online softmax ----
        float mx0 = NEG_INF, mx1 = NEG_INF;
#pragma unroll
        for (int nt = 0; nt < 8; nt++) {
            mx0 = fmaxf(mx0, fmaxf(s[nt][0], s[nt][1]));
            mx1 = fmaxf(mx1, fmaxf(s[nt][2], s[nt][3]));
        }
        mx0 = fmaxf(mx0, __shfl_xor_sync(0xffffffffu, mx0, 1));
        mx0 = fmaxf(mx0, __shfl_xor_sync(0xffffffffu, mx0, 2));
        mx1 = fmaxf(mx1, __shfl_xor_sync(0xffffffffu, mx1, 1));
        mx1 = fmaxf(mx1, __shfl_xor_sync(0xffffffffu, mx1, 2));
        float mn0 = fmaxf(m[0], mx0), mn1 = fmaxf(m[1], mx1);
        float al0 = __expf(m[0] - mn0), al1 = __expf(m[1] - mn1);
        m[0] = mn0; m[1] = mn1;
        float ps0 = 0.f, ps1 = 0.f;
#pragma unroll
        for (int nt = 0; nt < 8; nt++) {
            s[nt][0] = __expf(s[nt][0] - mn0); ps0 += s[nt][0];
            s[nt][1] = __expf(s[nt][1] - mn0); ps0 += s[nt][1];
            s[nt][2] = __expf(s[nt][2] - mn1); ps1 += s[nt][2];
            s[nt][3] = __expf(s[nt][3] - mn1); ps1 += s[nt][3];
        }
        ps0 += __shfl_xor_sync(0xffffffffu, ps0, 1);
        ps0 += __shfl_xor_sync(0xffffffffu, ps0, 2);
        ps1 += __shfl_xor_sync(0xffffffffu, ps1, 1);
        ps1 += __shfl_xor_sync(0xffffffffu, ps1, 2);
        l[0] = l[0] * al0 + ps0;
        l[1] = l[1] * al1 + ps1;
#pragma unroll
        for (int dt = 0; dt < 8; dt++) {
            o[dt][0] *= al0; o[dt][1] *= al0;
            o[dt][2] *= al1; o[dt][3] *= al1;
        }

        // ---- O += P V ----
#pragma unroll
        for (int kt = 0; kt < 4; kt++) {
            uint32_t ph[4], pl[4];
            ph[0] = bfpack(s[2*kt][0],   s[2*kt][1]);
            ph[1] = bfpack(s[2*kt][2],   s[2*kt][3]);
            ph[2] = bfpack(s[2*kt+1][0], s[2*kt+1][1]);
            ph[3] = bfpack(s[2*kt+1][2], s[2*kt+1][3]);
            pl[0] = bfpack(s[2*kt][0]   - lo_of(ph[0]), s[2*kt][1]   - hi_of(ph[0]));
            pl[1] = bfpack(s[2*kt][2]   - lo_of(ph[1]), s[2*kt][3]   - hi_of(ph[1]));
            pl[2] = bfpack(s[2*kt+1][0] - lo_of(ph[2]), s[2*kt+1][1] - hi_of(ph[2]));
            pl[3] = bfpack(s[2*kt+1][2] - lo_of(ph[3]), s[2*kt+1][3] - hi_of(ph[3]));
#pragma unroll
            for (int p = 0; p < 4; p++) {
                uint32_t off = (uint32_t)((p * 16 + f_row) * VS + kt * 8 + f_hk) * 4;
                uint32_t vh[4], vl[4];
                ldsm4(vh, sVh + off);
                ldsm4(vl, sVl + off);
                mma16816(o[2*p],   ph, vh);
                mma16816(o[2*p],   pl, vh);
                mma16816(o[2*p],   ph, vl);
                mma16816(o[2*p+1], ph, vh + 2);
                mma16816(o[2*p+1], pl, vh + 2);
                mma16816(o[2*p+1], ph, vl + 2);
            }
        }
    }

    // ---- epilogue ----
    float inv0 = 1.f / l[0], inv1 = 1.f / l[1];
#pragma unroll
    for (int dt = 0; dt < 8; dt++) {
        int col = headoff + dt * 8 + 2 * t;
        *(float2*)&g_a[(rowbase + g) * DM + col] =
            make_float2(o[dt][0] * inv0, o[dt][1] * inv0);
        *(float2*)&g_a[(rowbase + g + 8) * DM + col] =
            make_float2(o[dt][2] * inv1, o[dt][3] * inv1);
    }
}

// ---------------------------------------------------------------------------
extern "C" void kernel_launch(void* const* d_in, const int* in_sizes, int n_in,
                              void* d_out, int out_size)
{
    const float* x  = (const float*)d_in[0];
    const float* wq = (const float*)d_in[1];
    const float* wk = (const float*)d_in[2];
    const float* wv = (const float*)d_in[3];
    const float* wo = (const float*)d_in[4];
    float* out = (float*)d_out;

    float* a;
    cudaGetSymbolAddress((void**)&a, g_a);

    cudaFuncSetAttribute(flash_mma, cudaFuncAttributeMaxDynamicSharedMemorySize, FL_SMEM);

    gemm_qkv<<<dim3(DM / 128, MROWS / 128, 3), 256>>>(x, wq, wk, wv);
    flash_mma<<<dim3(SEQ / 128, NH, BATCH), 256, FL_SMEM>>>();
    gemm_mma<<<dim3(DM / 128, MROWS / 128), 256>>>(a, wo, out);
}